// round 3
// baseline (speedup 1.0000x reference)
#include <cuda_runtime.h>
#include <math.h>

#define NN 50000
#define EE 800000
#define DD 128

// ---------------- scratch (static __device__, no allocs) ----------------
__device__ float g_z[NN * DD];      // h @ W_func^T
__device__ float g_hs[NN * DD];     // h @ W_self^T
__device__ float g_ssrc[NN];
__device__ float g_sdst[NN];
__device__ float g_logits[EE];
__device__ int   g_deg[NN];
__device__ int   g_incl[NN];
__device__ int   g_bsum[64];
__device__ int   g_bbase[64];
__device__ int   g_cursor[NN];
__device__ int   g_off[NN + 1];
__device__ int   g_sorted[EE];

// ---------------- helpers ----------------
__device__ __forceinline__ unsigned f2tf(float x) {
    unsigned r;
    asm("cvt.rna.tf32.f32 %0, %1;" : "=r"(r) : "f"(x));
    return r;
}

__device__ __forceinline__ void mma_tf32(float* c, unsigned a0, unsigned a1,
                                         unsigned a2, unsigned a3,
                                         unsigned b0, unsigned b1) {
    asm volatile(
        "mma.sync.aligned.m16n8k8.row.col.f32.tf32.tf32.f32 "
        "{%0,%1,%2,%3},{%4,%5,%6,%7},{%8,%9},{%0,%1,%2,%3};\n"
        : "+f"(c[0]), "+f"(c[1]), "+f"(c[2]), "+f"(c[3])
        : "r"(a0), "r"(a1), "r"(a2), "r"(a3), "r"(b0), "r"(b1));
}

__device__ __forceinline__ float warp_sum(float v) {
    #pragma unroll
    for (int o = 16; o; o >>= 1) v += __shfl_xor_sync(0xFFFFFFFFu, v, o);
    return v;
}

// ---------------- K0: zero degree histogram ----------------
__global__ void k_zero_deg(int N) {
    int i = blockIdx.x * blockDim.x + threadIdx.x;
    if (i < N) g_deg[i] = 0;
}

// ---------------- K1: dual tf32 GEMM (h_s and z) ----------------
// Block: 256 threads (8 warps), tile 128 rows x 128 cols.
// Warp w handles rows [w*16, w*16+16). A frags held in registers.
__global__ __launch_bounds__(256, 1) void k_gemm_dual(
    const float* __restrict__ h, const float* __restrict__ Ws,
    const float* __restrict__ Wf, int N) {
    extern __shared__ float smem[];
    float* sH = smem;                                  // 128*132 f32
    unsigned* sW = (unsigned*)(smem + 128 * 132);      // 128*132 tf32 bits

    int tid = threadIdx.x;
    int lane = tid & 31, w = tid >> 5;
    int tg = lane & 3, gid = lane >> 2;
    int row0 = blockIdx.x * 128;

    // stage h tile (coalesced float4)
    for (int i = tid; i < 128 * 32; i += 256) {
        int r = i >> 5, c4 = i & 31;
        float4 v = make_float4(0.f, 0.f, 0.f, 0.f);
        if (row0 + r < N) v = ((const float4*)h)[(size_t)(row0 + r) * 32 + c4];
        *(float4*)&sH[r * 132 + c4 * 4] = v;
    }
    __syncthreads();

    // build A fragments: a[r][j] = A[w*16 + gid + 8r][tg + 4j]  (tf32)
    unsigned a[2][32];
    int ar0 = w * 16 + gid;
    #pragma unroll
    for (int j = 0; j < 32; j++) {
        a[0][j] = f2tf(sH[ar0 * 132 + tg + 4 * j]);
        a[1][j] = f2tf(sH[(ar0 + 8) * 132 + tg + 4 * j]);
    }

    const float* Wm[2] = {Ws, Wf};
    float* Om[2] = {g_hs, g_z};

    for (int m = 0; m < 2; m++) {
        __syncthreads();  // all warps done with previous sW before overwrite
        const float* W = Wm[m];
        for (int i = tid; i < 128 * 128; i += 256) {
            int r = i >> 7, c = i & 127;
            sW[r * 132 + c] = f2tf(W[i]);
        }
        __syncthreads();

        float acc[16][4];
        #pragma unroll
        for (int nt = 0; nt < 16; nt++)
            #pragma unroll
            for (int q = 0; q < 4; q++) acc[nt][q] = 0.f;

        #pragma unroll
        for (int kt = 0; kt < 16; kt++) {
            unsigned a0 = a[0][2 * kt], a2 = a[0][2 * kt + 1];
            unsigned a1 = a[1][2 * kt], a3 = a[1][2 * kt + 1];
            #pragma unroll
            for (int nt = 0; nt < 16; nt++) {
                unsigned b0 = sW[(nt * 8 + gid) * 132 + kt * 8 + tg];
                unsigned b1 = sW[(nt * 8 + gid) * 132 + kt * 8 + tg + 4];
                mma_tf32(acc[nt], a0, a1, a2, a3, b0, b1);
            }
        }

        float* O = Om[m];
        int r1 = row0 + ar0;
        int r2 = r1 + 8;
        #pragma unroll
        for (int nt = 0; nt < 16; nt++) {
            int col = nt * 8 + tg * 2;
            if (r1 < N) *(float2*)&O[(size_t)r1 * 128 + col] = make_float2(acc[nt][0], acc[nt][1]);
            if (r2 < N) *(float2*)&O[(size_t)r2 * 128 + col] = make_float2(acc[nt][2], acc[nt][3]);
        }
    }
}

// ---------------- K2: per-node attention dots s_src, s_dst ----------------
__global__ void k_rowdots(const float* __restrict__ Watt, int N) {
    int wid = (blockIdx.x * blockDim.x + threadIdx.x) >> 5;
    int lane = threadIdx.x & 31;
    if (wid >= N) return;
    float4 zv = ((const float4*)g_z)[(size_t)wid * 32 + lane];
    float4 wa = ((const float4*)Watt)[lane];        // wa[0:128]
    float4 wb = ((const float4*)Watt)[32 + lane];   // wa[128:256]
    float s1 = zv.x * wa.x + zv.y * wa.y + zv.z * wa.z + zv.w * wa.w;
    float s2 = zv.x * wb.x + zv.y * wb.y + zv.z * wb.z + zv.w * wb.w;
    s1 = warp_sum(s1);
    s2 = warp_sum(s2);
    if (lane == 0) { g_ssrc[wid] = s1; g_sdst[wid] = s2; }
}

// ---------------- K3: edge logits + degree histogram ----------------
__global__ void k_edge_logits(const float* __restrict__ ew,
                              const float* __restrict__ Watt,
                              const int* __restrict__ src,
                              const int* __restrict__ dst, int E) {
    int wid = (blockIdx.x * blockDim.x + threadIdx.x) >> 5;
    int lane = threadIdx.x & 31;
    if (wid >= E) return;
    float4 e4 = ((const float4*)ew)[(size_t)wid * 32 + lane];
    float4 w4 = ((const float4*)Watt)[64 + lane];   // wa[256:384]
    float s = e4.x * w4.x + e4.y * w4.y + e4.z * w4.z + e4.w * w4.w;
    s = warp_sum(s);
    if (lane == 0) {
        int d = dst[wid];
        float l = g_ssrc[src[wid]] + g_sdst[d] + s;
        g_logits[wid] = l > 0.f ? l : 0.01f * l;   // leaky_relu 0.01
        atomicAdd(&g_deg[d], 1);
    }
}

// ---------------- K4a/b/c: exclusive scan of degrees ----------------
__global__ void k_scan1(int N) {
    __shared__ int s[1024];
    int i = blockIdx.x * 1024 + threadIdx.x;
    int v = (i < N) ? g_deg[i] : 0;
    s[threadIdx.x] = v;
    #pragma unroll
    for (int off = 1; off < 1024; off <<= 1) {
        __syncthreads();
        int t = (threadIdx.x >= off) ? s[threadIdx.x - off] : 0;
        __syncthreads();
        s[threadIdx.x] += t;
    }
    if (i < N) g_incl[i] = s[threadIdx.x];
    if (threadIdx.x == 1023) g_bsum[blockIdx.x] = s[1023];
}

__global__ void k_scan2(int nb) {
    if (threadIdx.x == 0) {
        int base = 0;
        for (int b = 0; b < nb; b++) { g_bbase[b] = base; base += g_bsum[b]; }
    }
}

__global__ void k_scan3(int N, int E) {
    int i = blockIdx.x * blockDim.x + threadIdx.x;
    if (i >= N) return;
    int start = g_incl[i] - g_deg[i] + g_bbase[i >> 10];
    g_off[i] = start;
    g_cursor[i] = start;
    if (i == N - 1) g_off[N] = start + g_deg[i];
}

// ---------------- K5: scatter edge ids by dst (counting sort) ----------------
__global__ void k_scatter(const int* __restrict__ dst, int E) {
    int e = blockIdx.x * blockDim.x + threadIdx.x;
    if (e >= E) return;
    int d = dst[e];
    int p = atomicAdd(&g_cursor[d], 1);
    g_sorted[p] = e;
}

// ---------------- K6: per-dst softmax + weighted gather + epilogue ----------------
__global__ void k_aggregate(const float* __restrict__ h,
                            const int* __restrict__ src,
                            float* __restrict__ out, int N) {
    int wid = (blockIdx.x * blockDim.x + threadIdx.x) >> 5;
    int lane = threadIdx.x & 31;
    if (wid >= N) return;

    int beg = g_off[wid], end = g_off[wid + 1];
    float4 hv = ((const float4*)h)[(size_t)wid * 32 + lane];
    float4 res;

    if (beg == end) {
        // zero in-degree: h_new = relu(h_in); out = h_in + h_new
        res.x = hv.x + fmaxf(hv.x, 0.f);
        res.y = hv.y + fmaxf(hv.y, 0.f);
        res.z = hv.z + fmaxf(hv.z, 0.f);
        res.w = hv.w + fmaxf(hv.w, 0.f);
    } else {
        // pass 1: segment max
        float m = -INFINITY;
        for (int i = beg + lane; i < end; i += 32)
            m = fmaxf(m, g_logits[g_sorted[i]]);
        #pragma unroll
        for (int o = 16; o; o >>= 1)
            m = fmaxf(m, __shfl_xor_sync(0xFFFFFFFFu, m, o));

        // pass 2: exp-sum + weighted accumulation (lane owns 4 cols)
        float4 acc = make_float4(0.f, 0.f, 0.f, 0.f);
        float denom = 0.f;
        for (int i = beg; i < end; i++) {
            int e = g_sorted[i];                       // broadcast load
            float wgt = expf(g_logits[e] - m);
            denom += wgt;
            float4 zv = ((const float4*)g_z)[(size_t)src[e] * 32 + lane];
            acc.x += wgt * zv.x;
            acc.y += wgt * zv.y;
            acc.z += wgt * zv.z;
            acc.w += wgt * zv.w;
        }
        float inv = 1.f / fmaxf(denom, 1e-9f);
        float4 hs = ((const float4*)g_hs)[(size_t)wid * 32 + lane];
        float tx = hs.x + acc.x * inv;
        float ty = hs.y + acc.y * inv;
        float tz = hs.z + acc.z * inv;
        float tw = hs.w + acc.w * inv;
        res.x = hv.x + fmaxf(tx, 0.f);
        res.y = hv.y + fmaxf(ty, 0.f);
        res.z = hv.z + fmaxf(tz, 0.f);
        res.w = hv.w + fmaxf(tw, 0.f);
    }
    ((float4*)out)[(size_t)wid * 32 + lane] = res;
}

// ---------------- launch ----------------
extern "C" void kernel_launch(void* const* d_in, const int* in_sizes, int n_in,
                              void* d_out, int out_size) {
    const float* h    = (const float*)d_in[0];
    const float* ew   = (const float*)d_in[1];
    const float* Ws   = (const float*)d_in[2];
    const float* Wf   = (const float*)d_in[3];
    const float* Watt = (const float*)d_in[4];
    const int*   src  = (const int*)d_in[5];
    const int*   dst  = (const int*)d_in[6];
    float* out = (float*)d_out;

    int N = in_sizes[0] / DD;
    int E = in_sizes[5];

    static bool attr_set = false;
    size_t gemm_smem = (size_t)(128 * 132) * 4 * 2;  // sH f32 + sW tf32
    cudaFuncSetAttribute(k_gemm_dual, cudaFuncAttributeMaxDynamicSharedMemorySize,
                         (int)gemm_smem);
    (void)attr_set;

    k_zero_deg<<<(N + 255) / 256, 256>>>(N);
    k_gemm_dual<<<(N + 127) / 128, 256, gemm_smem>>>(h, Ws, Wf, N);
    k_rowdots<<<(N + 7) / 8, 256>>>(Watt, N);
    k_edge_logits<<<(E + 7) / 8, 256>>>(ew, Watt, src, dst, E);

    int nb = (N + 1023) / 1024;
    k_scan1<<<nb, 1024>>>(N);
    k_scan2<<<1, 32>>>(nb);
    k_scan3<<<(N + 255) / 256, 256>>>(N, E);
    k_scatter<<<(E + 255) / 256, 256>>>(dst, E);
    k_aggregate<<<(N + 7) / 8, 256>>>(h, src, out, N);
}

// round 7
// speedup vs baseline: 1.2025x; 1.2025x over previous
#include <cuda_runtime.h>
#include <math.h>

#define NN 50000
#define EE 800000
#define DD 128

// ---------------- scratch (static __device__, no allocs) ----------------
__device__ float g_z[NN * DD];      // h @ W_func^T
__device__ float g_hs[NN * DD];     // h @ W_self^T
__device__ float g_ssrc[NN];
__device__ float g_sdst[NN];
__device__ float g_logits[EE];
__device__ int   g_deg[NN];
__device__ int   g_incl[NN];
__device__ int   g_bsum[64];
__device__ int   g_bbase[64];
__device__ int   g_cursor[NN];
__device__ int   g_off[NN + 1];
__device__ float g_slog[EE];        // logits sorted by dst
__device__ int   g_ssrc2[EE];       // src ids sorted by dst

// ---------------- helpers ----------------
__device__ __forceinline__ unsigned f2tf(float x) {
    unsigned r;
    asm("cvt.rna.tf32.f32 %0, %1;" : "=r"(r) : "f"(x));
    return r;
}

__device__ __forceinline__ void mma_tf32(float* c, unsigned a0, unsigned a1,
                                         unsigned a2, unsigned a3,
                                         unsigned b0, unsigned b1) {
    asm volatile(
        "mma.sync.aligned.m16n8k8.row.col.f32.tf32.tf32.f32 "
        "{%0,%1,%2,%3},{%4,%5,%6,%7},{%8,%9},{%0,%1,%2,%3};\n"
        : "+f"(c[0]), "+f"(c[1]), "+f"(c[2]), "+f"(c[3])
        : "r"(a0), "r"(a1), "r"(a2), "r"(a3), "r"(b0), "r"(b1));
}

__device__ __forceinline__ float warp_sum(float v) {
    #pragma unroll
    for (int o = 16; o; o >>= 1) v += __shfl_xor_sync(0xFFFFFFFFu, v, o);
    return v;
}

// ---------------- K0: zero degree histogram ----------------
__global__ void k_zero_deg(int N) {
    int i = blockIdx.x * blockDim.x + threadIdx.x;
    if (i < N) g_deg[i] = 0;
}

// ---------------- K1: dual tf32 GEMM (h_s and z) ----------------
__global__ __launch_bounds__(256, 1) void k_gemm_dual(
    const float* __restrict__ h, const float* __restrict__ Ws,
    const float* __restrict__ Wf, int N) {
    extern __shared__ float smem[];
    float* sH = smem;                                  // 128*132 f32
    unsigned* sW = (unsigned*)(smem + 128 * 132);      // 128*132 tf32 bits

    int tid = threadIdx.x;
    int lane = tid & 31, w = tid >> 5;
    int tg = lane & 3, gid = lane >> 2;
    int row0 = blockIdx.x * 128;

    for (int i = tid; i < 128 * 32; i += 256) {
        int r = i >> 5, c4 = i & 31;
        float4 v = make_float4(0.f, 0.f, 0.f, 0.f);
        if (row0 + r < N) v = ((const float4*)h)[(size_t)(row0 + r) * 32 + c4];
        *(float4*)&sH[r * 132 + c4 * 4] = v;
    }
    __syncthreads();

    unsigned a[2][32];
    int ar0 = w * 16 + gid;
    #pragma unroll
    for (int j = 0; j < 32; j++) {
        a[0][j] = f2tf(sH[ar0 * 132 + tg + 4 * j]);
        a[1][j] = f2tf(sH[(ar0 + 8) * 132 + tg + 4 * j]);
    }

    const float* Wm[2] = {Ws, Wf};
    float* Om[2] = {g_hs, g_z};

    for (int m = 0; m < 2; m++) {
        __syncthreads();
        const float* W = Wm[m];
        for (int i = tid; i < 128 * 128; i += 256) {
            int r = i >> 7, c = i & 127;
            sW[r * 132 + c] = f2tf(W[i]);
        }
        __syncthreads();

        float acc[16][4];
        #pragma unroll
        for (int nt = 0; nt < 16; nt++)
            #pragma unroll
            for (int q = 0; q < 4; q++) acc[nt][q] = 0.f;

        #pragma unroll
        for (int kt = 0; kt < 16; kt++) {
            unsigned a0 = a[0][2 * kt], a2 = a[0][2 * kt + 1];
            unsigned a1 = a[1][2 * kt], a3 = a[1][2 * kt + 1];
            #pragma unroll
            for (int nt = 0; nt < 16; nt++) {
                unsigned b0 = sW[(nt * 8 + gid) * 132 + kt * 8 + tg];
                unsigned b1 = sW[(nt * 8 + gid) * 132 + kt * 8 + tg + 4];
                mma_tf32(acc[nt], a0, a1, a2, a3, b0, b1);
            }
        }

        float* O = Om[m];
        int r1 = row0 + ar0;
        int r2 = r1 + 8;
        #pragma unroll
        for (int nt = 0; nt < 16; nt++) {
            int col = nt * 8 + tg * 2;
            if (r1 < N) *(float2*)&O[(size_t)r1 * 128 + col] = make_float2(acc[nt][0], acc[nt][1]);
            if (r2 < N) *(float2*)&O[(size_t)r2 * 128 + col] = make_float2(acc[nt][2], acc[nt][3]);
        }
    }
}

// ---------------- K2: per-node attention dots s_src, s_dst ----------------
__global__ void k_rowdots(const float* __restrict__ Watt, int N) {
    int wid = (blockIdx.x * blockDim.x + threadIdx.x) >> 5;
    int lane = threadIdx.x & 31;
    if (wid >= N) return;
    float4 zv = ((const float4*)g_z)[(size_t)wid * 32 + lane];
    float4 wa = ((const float4*)Watt)[lane];
    float4 wb = ((const float4*)Watt)[32 + lane];
    float s1 = zv.x * wa.x + zv.y * wa.y + zv.z * wa.z + zv.w * wa.w;
    float s2 = zv.x * wb.x + zv.y * wb.y + zv.z * wb.z + zv.w * wb.w;
    s1 = warp_sum(s1);
    s2 = warp_sum(s2);
    if (lane == 0) { g_ssrc[wid] = s1; g_sdst[wid] = s2; }
}

// ---------------- K3: edge logits (4 edges/warp for MLP=4) + degree ----------------
__global__ void k_edge_logits(const float* __restrict__ ew,
                              const float* __restrict__ Watt,
                              const int* __restrict__ src,
                              const int* __restrict__ dst, int E) {
    int wid = (blockIdx.x * blockDim.x + threadIdx.x) >> 5;
    int lane = threadIdx.x & 31;
    int base = wid * 4;
    if (base >= E) return;

    float4 w4 = ((const float4*)Watt)[64 + lane];   // wa[256:384]

    // 4 independent float4 loads up front (MLP=4)
    float4 e0 = make_float4(0,0,0,0), e1 = e0, e2 = e0, e3 = e0;
    e0 = ((const float4*)ew)[(size_t)base * 32 + lane];
    if (base + 1 < E) e1 = ((const float4*)ew)[(size_t)(base + 1) * 32 + lane];
    if (base + 2 < E) e2 = ((const float4*)ew)[(size_t)(base + 2) * 32 + lane];
    if (base + 3 < E) e3 = ((const float4*)ew)[(size_t)(base + 3) * 32 + lane];

    float s0 = e0.x * w4.x + e0.y * w4.y + e0.z * w4.z + e0.w * w4.w;
    float s1 = e1.x * w4.x + e1.y * w4.y + e1.z * w4.z + e1.w * w4.w;
    float s2 = e2.x * w4.x + e2.y * w4.y + e2.z * w4.z + e2.w * w4.w;
    float s3 = e3.x * w4.x + e3.y * w4.y + e3.z * w4.z + e3.w * w4.w;

    // interleaved butterflies (ILP=4)
    #pragma unroll
    for (int o = 16; o; o >>= 1) {
        s0 += __shfl_xor_sync(0xFFFFFFFFu, s0, o);
        s1 += __shfl_xor_sync(0xFFFFFFFFu, s1, o);
        s2 += __shfl_xor_sync(0xFFFFFFFFu, s2, o);
        s3 += __shfl_xor_sync(0xFFFFFFFFu, s3, o);
    }

    // epilogue parallelized across lanes 0-3
    if (lane < 4) {
        int e = base + lane;
        if (e < E) {
            float se = lane == 0 ? s0 : lane == 1 ? s1 : lane == 2 ? s2 : s3;
            int d = dst[e];
            float l = g_ssrc[src[e]] + g_sdst[d] + se;
            g_logits[e] = l > 0.f ? l : 0.01f * l;
            atomicAdd(&g_deg[d], 1);
        }
    }
}

// ---------------- K4a/b/c: exclusive scan of degrees ----------------
__global__ void k_scan1(int N) {
    __shared__ int s[1024];
    int i = blockIdx.x * 1024 + threadIdx.x;
    int v = (i < N) ? g_deg[i] : 0;
    s[threadIdx.x] = v;
    #pragma unroll
    for (int off = 1; off < 1024; off <<= 1) {
        __syncthreads();
        int t = (threadIdx.x >= off) ? s[threadIdx.x - off] : 0;
        __syncthreads();
        s[threadIdx.x] += t;
    }
    if (i < N) g_incl[i] = s[threadIdx.x];
    if (threadIdx.x == 1023) g_bsum[blockIdx.x] = s[1023];
}

__global__ void k_scan2(int nb) {
    if (threadIdx.x == 0) {
        int base = 0;
        for (int b = 0; b < nb; b++) { g_bbase[b] = base; base += g_bsum[b]; }
    }
}

__global__ void k_scan3(int N, int E) {
    int i = blockIdx.x * blockDim.x + threadIdx.x;
    if (i >= N) return;
    int start = g_incl[i] - g_deg[i] + g_bbase[i >> 10];
    g_off[i] = start;
    g_cursor[i] = start;
    if (i == N - 1) g_off[N] = start + g_deg[i];
}

// ---------------- K5: scatter logit+src into dst-sorted order ----------------
__global__ void k_scatter(const int* __restrict__ dst,
                          const int* __restrict__ src, int E) {
    int e = blockIdx.x * blockDim.x + threadIdx.x;
    if (e >= E) return;
    int d = dst[e];
    int p = atomicAdd(&g_cursor[d], 1);
    g_slog[p] = g_logits[e];
    g_ssrc2[p] = src[e];
}

// ---------------- K6: per-dst softmax + weighted gather + epilogue ----------------
__global__ void k_aggregate(const float* __restrict__ h,
                            float* __restrict__ out, int N) {
    int wid = (blockIdx.x * blockDim.x + threadIdx.x) >> 5;
    int lane = threadIdx.x & 31;
    if (wid >= N) return;

    int beg = g_off[wid], end = g_off[wid + 1];
    float4 hv = ((const float4*)h)[(size_t)wid * 32 + lane];
    float4 res;

    if (beg == end) {
        res.x = hv.x + fmaxf(hv.x, 0.f);
        res.y = hv.y + fmaxf(hv.y, 0.f);
        res.z = hv.z + fmaxf(hv.z, 0.f);
        res.w = hv.w + fmaxf(hv.w, 0.f);
    } else {
        // pass 1: segment max (coalesced sequential reads)
        float m = -INFINITY;
        for (int i = beg + lane; i < end; i += 32)
            m = fmaxf(m, g_slog[i]);
        #pragma unroll
        for (int o = 16; o; o >>= 1)
            m = fmaxf(m, __shfl_xor_sync(0xFFFFFFFFu, m, o));

        // pass 2: chunked, MLP=4 z-gathers, per-lane denom
        float4 acc = make_float4(0.f, 0.f, 0.f, 0.f);
        float denom = 0.f;
        for (int i = beg; i < end; i += 32) {
            int cnt = end - i; if (cnt > 32) cnt = 32;
            float wl = 0.f;
            int sv = 0;
            if (lane < cnt) {
                wl = __expf(g_slog[i + lane] - m);
                sv = g_ssrc2[i + lane];
            }
            denom += wl;
            int k = 0;
            for (; k + 4 <= cnt; k += 4) {
                float w0 = __shfl_sync(0xFFFFFFFFu, wl, k);
                float w1 = __shfl_sync(0xFFFFFFFFu, wl, k + 1);
                float w2 = __shfl_sync(0xFFFFFFFFu, wl, k + 2);
                float w3 = __shfl_sync(0xFFFFFFFFu, wl, k + 3);
                int   a0 = __shfl_sync(0xFFFFFFFFu, sv, k);
                int   a1 = __shfl_sync(0xFFFFFFFFu, sv, k + 1);
                int   a2 = __shfl_sync(0xFFFFFFFFu, sv, k + 2);
                int   a3 = __shfl_sync(0xFFFFFFFFu, sv, k + 3);
                float4 z0 = ((const float4*)g_z)[(size_t)a0 * 32 + lane];
                float4 z1 = ((const float4*)g_z)[(size_t)a1 * 32 + lane];
                float4 z2 = ((const float4*)g_z)[(size_t)a2 * 32 + lane];
                float4 z3 = ((const float4*)g_z)[(size_t)a3 * 32 + lane];
                acc.x += w0 * z0.x + w1 * z1.x + w2 * z2.x + w3 * z3.x;
                acc.y += w0 * z0.y + w1 * z1.y + w2 * z2.y + w3 * z3.y;
                acc.z += w0 * z0.z + w1 * z1.z + w2 * z2.z + w3 * z3.z;
                acc.w += w0 * z0.w + w1 * z1.w + w2 * z2.w + w3 * z3.w;
            }
            for (; k < cnt; k++) {
                float w0 = __shfl_sync(0xFFFFFFFFu, wl, k);
                int   a0 = __shfl_sync(0xFFFFFFFFu, sv, k);
                float4 z0 = ((const float4*)g_z)[(size_t)a0 * 32 + lane];
                acc.x += w0 * z0.x;
                acc.y += w0 * z0.y;
                acc.z += w0 * z0.z;
                acc.w += w0 * z0.w;
            }
        }
        denom = warp_sum(denom);
        float inv = 1.f / fmaxf(denom, 1e-9f);
        float4 hs = ((const float4*)g_hs)[(size_t)wid * 32 + lane];
        float tx = hs.x + acc.x * inv;
        float ty = hs.y + acc.y * inv;
        float tz = hs.z + acc.z * inv;
        float tw = hs.w + acc.w * inv;
        res.x = hv.x + fmaxf(tx, 0.f);
        res.y = hv.y + fmaxf(ty, 0.f);
        res.z = hv.z + fmaxf(tz, 0.f);
        res.w = hv.w + fmaxf(tw, 0.f);
    }
    ((float4*)out)[(size_t)wid * 32 + lane] = res;
}

// ---------------- launch ----------------
extern "C" void kernel_launch(void* const* d_in, const int* in_sizes, int n_in,
                              void* d_out, int out_size) {
    const float* h    = (const float*)d_in[0];
    const float* ew   = (const float*)d_in[1];
    const float* Ws   = (const float*)d_in[2];
    const float* Wf   = (const float*)d_in[3];
    const float* Watt = (const float*)d_in[4];
    const int*   src  = (const int*)d_in[5];
    const int*   dst  = (const int*)d_in[6];
    float* out = (float*)d_out;

    int N = in_sizes[0] / DD;
    int E = in_sizes[5];

    size_t gemm_smem = (size_t)(128 * 132) * 4 * 2;
    cudaFuncSetAttribute(k_gemm_dual, cudaFuncAttributeMaxDynamicSharedMemorySize,
                         (int)gemm_smem);

    k_zero_deg<<<(N + 255) / 256, 256>>>(N);
    k_gemm_dual<<<(N + 127) / 128, 256, gemm_smem>>>(h, Ws, Wf, N);
    k_rowdots<<<(N + 7) / 8, 256>>>(Watt, N);

    int ewarps = (E + 3) / 4;
    k_edge_logits<<<(ewarps + 7) / 8, 256>>>(ew, Watt, src, dst, E);

    int nb = (N + 1023) / 1024;
    k_scan1<<<nb, 1024>>>(N);
    k_scan2<<<1, 32>>>(nb);
    k_scan3<<<(N + 255) / 256, 256>>>(N, E);
    k_scatter<<<(E + 255) / 256, 256>>>(dst, src, E);
    k_aggregate<<<(N + 7) / 8, 256>>>(h, out, N);
}

// round 8
// speedup vs baseline: 1.2451x; 1.0355x over previous
#include <cuda_runtime.h>
#include <math.h>

#define NN 50000
#define EE 800000
#define DD 128

// ---------------- scratch (static __device__, no allocs) ----------------
__device__ float g_z[NN * DD];      // h @ W_func^T
__device__ float g_hs[NN * DD];     // h @ W_self^T
__device__ float g_ssrc[NN];
__device__ float g_sdst[NN];
__device__ float g_logits[EE];
__device__ int   g_deg[NN];
__device__ int   g_incl[NN];
__device__ int   g_bsum[64];
__device__ int   g_bbase[64];
__device__ int   g_cursor[NN];
__device__ int   g_off[NN + 1];
__device__ unsigned long long g_pair[EE];   // (logit<<32 | src) sorted by dst

// ---------------- helpers ----------------
__device__ __forceinline__ unsigned f2tf(float x) {
    unsigned r;
    asm("cvt.rna.tf32.f32 %0, %1;" : "=r"(r) : "f"(x));
    return r;
}

__device__ __forceinline__ void mma_tf32(float* c, unsigned a0, unsigned a1,
                                         unsigned a2, unsigned a3,
                                         unsigned b0, unsigned b1) {
    asm volatile(
        "mma.sync.aligned.m16n8k8.row.col.f32.tf32.tf32.f32 "
        "{%0,%1,%2,%3},{%4,%5,%6,%7},{%8,%9},{%0,%1,%2,%3};\n"
        : "+f"(c[0]), "+f"(c[1]), "+f"(c[2]), "+f"(c[3])
        : "r"(a0), "r"(a1), "r"(a2), "r"(a3), "r"(b0), "r"(b1));
}

__device__ __forceinline__ float warp_sum(float v) {
    #pragma unroll
    for (int o = 16; o; o >>= 1) v += __shfl_xor_sync(0xFFFFFFFFu, v, o);
    return v;
}

// ---------------- K0: zero degree histogram ----------------
__global__ void k_zero_deg(int N) {
    int i = blockIdx.x * blockDim.x + threadIdx.x;
    if (i < N) g_deg[i] = 0;
}

// ---------------- K1: dual tf32 GEMM (h_s and z) + fused rowdots ----------------
__global__ __launch_bounds__(256, 1) void k_gemm_dual(
    const float* __restrict__ h, const float* __restrict__ Ws,
    const float* __restrict__ Wf, const float* __restrict__ Watt, int N) {
    extern __shared__ float smem[];
    float* sH = smem;                                  // 128*132 f32
    unsigned* sW = (unsigned*)(smem + 128 * 132);      // 128*132 tf32 bits

    int tid = threadIdx.x;
    int lane = tid & 31, w = tid >> 5;
    int tg = lane & 3, gid = lane >> 2;
    int row0 = blockIdx.x * 128;

    for (int i = tid; i < 128 * 32; i += 256) {
        int r = i >> 5, c4 = i & 31;
        float4 v = make_float4(0.f, 0.f, 0.f, 0.f);
        if (row0 + r < N) v = ((const float4*)h)[(size_t)(row0 + r) * 32 + c4];
        *(float4*)&sH[r * 132 + c4 * 4] = v;
    }
    __syncthreads();

    unsigned a[2][32];
    int ar0 = w * 16 + gid;
    #pragma unroll
    for (int j = 0; j < 32; j++) {
        a[0][j] = f2tf(sH[ar0 * 132 + tg + 4 * j]);
        a[1][j] = f2tf(sH[(ar0 + 8) * 132 + tg + 4 * j]);
    }

    const float* Wm[2] = {Ws, Wf};
    float* Om[2] = {g_hs, g_z};

    for (int m = 0; m < 2; m++) {
        __syncthreads();
        const float* W = Wm[m];
        for (int i = tid; i < 128 * 128; i += 256) {
            int r = i >> 7, c = i & 127;
            sW[r * 132 + c] = f2tf(W[i]);
        }
        __syncthreads();

        float acc[16][4];
        #pragma unroll
        for (int nt = 0; nt < 16; nt++)
            #pragma unroll
            for (int q = 0; q < 4; q++) acc[nt][q] = 0.f;

        #pragma unroll
        for (int kt = 0; kt < 16; kt++) {
            unsigned a0 = a[0][2 * kt], a2 = a[0][2 * kt + 1];
            unsigned a1 = a[1][2 * kt], a3 = a[1][2 * kt + 1];
            #pragma unroll
            for (int nt = 0; nt < 16; nt++) {
                unsigned b0 = sW[(nt * 8 + gid) * 132 + kt * 8 + tg];
                unsigned b1 = sW[(nt * 8 + gid) * 132 + kt * 8 + tg + 4];
                mma_tf32(acc[nt], a0, a1, a2, a3, b0, b1);
            }
        }

        float* O = Om[m];
        int r1 = row0 + ar0;
        int r2 = r1 + 8;
        #pragma unroll
        for (int nt = 0; nt < 16; nt++) {
            int col = nt * 8 + tg * 2;
            if (r1 < N) *(float2*)&O[(size_t)r1 * 128 + col] = make_float2(acc[nt][0], acc[nt][1]);
            if (r2 < N) *(float2*)&O[(size_t)r2 * 128 + col] = make_float2(acc[nt][2], acc[nt][3]);
        }

        if (m == 1) {
            // fused rowdots: s_src = z·Wa[0:128], s_dst = z·Wa[128:256]
            float p1a = 0.f, p1b = 0.f, p2a = 0.f, p2b = 0.f;
            #pragma unroll
            for (int nt = 0; nt < 16; nt++) {
                int c0 = nt * 8 + tg * 2;
                float wa0 = Watt[c0],        wa1 = Watt[c0 + 1];
                float wb0 = Watt[128 + c0],  wb1 = Watt[128 + c0 + 1];
                p1a += acc[nt][0] * wa0 + acc[nt][1] * wa1;   // row r1, s_src
                p1b += acc[nt][0] * wb0 + acc[nt][1] * wb1;   // row r1, s_dst
                p2a += acc[nt][2] * wa0 + acc[nt][3] * wa1;   // row r2, s_src
                p2b += acc[nt][2] * wb0 + acc[nt][3] * wb1;   // row r2, s_dst
            }
            // reduce across the 4 lanes of the tg-group (lane = gid*4 + tg)
            #pragma unroll
            for (int o = 1; o < 4; o <<= 1) {
                p1a += __shfl_xor_sync(0xFFFFFFFFu, p1a, o);
                p1b += __shfl_xor_sync(0xFFFFFFFFu, p1b, o);
                p2a += __shfl_xor_sync(0xFFFFFFFFu, p2a, o);
                p2b += __shfl_xor_sync(0xFFFFFFFFu, p2b, o);
            }
            if (tg == 0) {
                if (r1 < N) { g_ssrc[r1] = p1a; g_sdst[r1] = p1b; }
                if (r2 < N) { g_ssrc[r2] = p2a; g_sdst[r2] = p2b; }
            }
        }
    }
}

// ---------------- K3: edge logits (8 edges/warp, MLP=8) + degree ----------------
__global__ void k_edge_logits(const float* __restrict__ ew,
                              const float* __restrict__ Watt,
                              const int* __restrict__ src,
                              const int* __restrict__ dst, int E) {
    int wid = (blockIdx.x * blockDim.x + threadIdx.x) >> 5;
    int lane = threadIdx.x & 31;
    int base = wid * 8;
    if (base >= E) return;

    float4 w4 = ((const float4*)Watt)[64 + lane];   // wa[256:384]

    float s[8];
    #pragma unroll
    for (int j = 0; j < 8; j++) {
        float4 e4 = make_float4(0.f, 0.f, 0.f, 0.f);
        if (base + j < E) e4 = ((const float4*)ew)[(size_t)(base + j) * 32 + lane];
        s[j] = e4.x * w4.x + e4.y * w4.y + e4.z * w4.z + e4.w * w4.w;
    }

    #pragma unroll
    for (int o = 16; o; o >>= 1) {
        #pragma unroll
        for (int j = 0; j < 8; j++)
            s[j] += __shfl_xor_sync(0xFFFFFFFFu, s[j], o);
    }

    if (lane < 8) {
        int e = base + lane;
        if (e < E) {
            float se = s[0];
            #pragma unroll
            for (int j = 1; j < 8; j++)
                if (lane == j) se = s[j];
            int d = dst[e];
            float l = g_ssrc[src[e]] + g_sdst[d] + se;
            g_logits[e] = l > 0.f ? l : 0.01f * l;
            atomicAdd(&g_deg[d], 1);
        }
    }
}

// ---------------- K4a/b/c: exclusive scan of degrees ----------------
__global__ void k_scan1(int N) {
    __shared__ int s[1024];
    int i = blockIdx.x * 1024 + threadIdx.x;
    int v = (i < N) ? g_deg[i] : 0;
    s[threadIdx.x] = v;
    #pragma unroll
    for (int off = 1; off < 1024; off <<= 1) {
        __syncthreads();
        int t = (threadIdx.x >= off) ? s[threadIdx.x - off] : 0;
        __syncthreads();
        s[threadIdx.x] += t;
    }
    if (i < N) g_incl[i] = s[threadIdx.x];
    if (threadIdx.x == 1023) g_bsum[blockIdx.x] = s[1023];
}

__global__ void k_scan2(int nb) {
    if (threadIdx.x == 0) {
        int base = 0;
        for (int b = 0; b < nb; b++) { g_bbase[b] = base; base += g_bsum[b]; }
    }
}

__global__ void k_scan3(int N, int E) {
    int i = blockIdx.x * blockDim.x + threadIdx.x;
    if (i >= N) return;
    int start = g_incl[i] - g_deg[i] + g_bbase[i >> 10];
    g_off[i] = start;
    g_cursor[i] = start;
    if (i == N - 1) g_off[N] = start + g_deg[i];
}

// ---------------- K5: scatter packed (logit,src) into dst-sorted order ----------------
__global__ void k_scatter(const int* __restrict__ dst,
                          const int* __restrict__ src, int E) {
    int e = blockIdx.x * blockDim.x + threadIdx.x;
    if (e >= E) return;
    int d = dst[e];
    int p = atomicAdd(&g_cursor[d], 1);
    unsigned long long u =
        ((unsigned long long)__float_as_uint(g_logits[e]) << 32) |
        (unsigned)src[e];
    g_pair[p] = u;
}

// ---------------- K6: per-dst softmax + weighted gather + epilogue ----------------
__global__ void k_aggregate(const float* __restrict__ h,
                            float* __restrict__ out, int N) {
    int wid = (blockIdx.x * blockDim.x + threadIdx.x) >> 5;
    int lane = threadIdx.x & 31;
    if (wid >= N) return;

    int beg = g_off[wid], end = g_off[wid + 1];
    float4 hv = ((const float4*)h)[(size_t)wid * 32 + lane];
    float4 res;

    if (beg == end) {
        res.x = hv.x + fmaxf(hv.x, 0.f);
        res.y = hv.y + fmaxf(hv.y, 0.f);
        res.z = hv.z + fmaxf(hv.z, 0.f);
        res.w = hv.w + fmaxf(hv.w, 0.f);
    } else {
        // pass 1: segment max (coalesced 8B reads)
        float m = -INFINITY;
        for (int i = beg + lane; i < end; i += 32)
            m = fmaxf(m, __uint_as_float((unsigned)(g_pair[i] >> 32)));
        #pragma unroll
        for (int o = 16; o; o >>= 1)
            m = fmaxf(m, __shfl_xor_sync(0xFFFFFFFFu, m, o));

        // pass 2: chunked, 8 z-rows in flight, per-lane denom
        float4 acc = make_float4(0.f, 0.f, 0.f, 0.f);
        float denom = 0.f;
        for (int i = beg; i < end; i += 32) {
            int cnt = end - i; if (cnt > 32) cnt = 32;
            float wl = 0.f;
            int sv = 0;
            if (lane < cnt) {
                unsigned long long u = g_pair[i + lane];
                wl = __expf(__uint_as_float((unsigned)(u >> 32)) - m);
                sv = (int)(unsigned)u;
            }
            denom += wl;
            int k = 0;
            for (; k + 8 <= cnt; k += 8) {
                float wb[8]; int ab[8];
                #pragma unroll
                for (int j = 0; j < 8; j++) {
                    wb[j] = __shfl_sync(0xFFFFFFFFu, wl, k + j);
                    ab[j] = __shfl_sync(0xFFFFFFFFu, sv, k + j);
                }
                float4 zb[8];
                #pragma unroll
                for (int j = 0; j < 8; j++)
                    zb[j] = ((const float4*)g_z)[(size_t)ab[j] * 32 + lane];
                #pragma unroll
                for (int j = 0; j < 8; j++) {
                    acc.x += wb[j] * zb[j].x;
                    acc.y += wb[j] * zb[j].y;
                    acc.z += wb[j] * zb[j].z;
                    acc.w += wb[j] * zb[j].w;
                }
            }
            for (; k + 4 <= cnt; k += 4) {
                float wb[4]; int ab[4];
                #pragma unroll
                for (int j = 0; j < 4; j++) {
                    wb[j] = __shfl_sync(0xFFFFFFFFu, wl, k + j);
                    ab[j] = __shfl_sync(0xFFFFFFFFu, sv, k + j);
                }
                float4 zb[4];
                #pragma unroll
                for (int j = 0; j < 4; j++)
                    zb[j] = ((const float4*)g_z)[(size_t)ab[j] * 32 + lane];
                #pragma unroll
                for (int j = 0; j < 4; j++) {
                    acc.x += wb[j] * zb[j].x;
                    acc.y += wb[j] * zb[j].y;
                    acc.z += wb[j] * zb[j].z;
                    acc.w += wb[j] * zb[j].w;
                }
            }
            for (; k < cnt; k++) {
                float w0 = __shfl_sync(0xFFFFFFFFu, wl, k);
                int   a0 = __shfl_sync(0xFFFFFFFFu, sv, k);
                float4 z0 = ((const float4*)g_z)[(size_t)a0 * 32 + lane];
                acc.x += w0 * z0.x;
                acc.y += w0 * z0.y;
                acc.z += w0 * z0.z;
                acc.w += w0 * z0.w;
            }
        }
        denom = warp_sum(denom);
        float inv = 1.f / fmaxf(denom, 1e-9f);
        float4 hs = ((const float4*)g_hs)[(size_t)wid * 32 + lane];
        float tx = hs.x + acc.x * inv;
        float ty = hs.y + acc.y * inv;
        float tz = hs.z + acc.z * inv;
        float tw = hs.w + acc.w * inv;
        res.x = hv.x + fmaxf(tx, 0.f);
        res.y = hv.y + fmaxf(ty, 0.f);
        res.z = hv.z + fmaxf(tz, 0.f);
        res.w = hv.w + fmaxf(tw, 0.f);
    }
    ((float4*)out)[(size_t)wid * 32 + lane] = res;
}

// ---------------- launch ----------------
extern "C" void kernel_launch(void* const* d_in, const int* in_sizes, int n_in,
                              void* d_out, int out_size) {
    const float* h    = (const float*)d_in[0];
    const float* ew   = (const float*)d_in[1];
    const float* Ws   = (const float*)d_in[2];
    const float* Wf   = (const float*)d_in[3];
    const float* Watt = (const float*)d_in[4];
    const int*   src  = (const int*)d_in[5];
    const int*   dst  = (const int*)d_in[6];
    float* out = (float*)d_out;

    int N = in_sizes[0] / DD;
    int E = in_sizes[5];

    size_t gemm_smem = (size_t)(128 * 132) * 4 * 2;
    cudaFuncSetAttribute(k_gemm_dual, cudaFuncAttributeMaxDynamicSharedMemorySize,
                         (int)gemm_smem);

    k_zero_deg<<<(N + 255) / 256, 256>>>(N);
    k_gemm_dual<<<(N + 127) / 128, 256, gemm_smem>>>(h, Ws, Wf, Watt, N);

    int ewarps = (E + 7) / 8;
    k_edge_logits<<<(ewarps + 7) / 8, 256>>>(ew, Watt, src, dst, E);

    int nb = (N + 1023) / 1024;
    k_scan1<<<nb, 1024>>>(N);
    k_scan2<<<1, 32>>>(nb);
    k_scan3<<<(N + 255) / 256, 256>>>(N, E);
    k_scatter<<<(E + 255) / 256, 256>>>(dst, src, E);
    k_aggregate<<<(N + 7) / 8, 256>>>(h, out, N);
}

// round 9
// speedup vs baseline: 1.2543x; 1.0073x over previous
#include <cuda_runtime.h>
#include <math.h>

#define NN 50000
#define EE 800000
#define DD 128

// ---------------- scratch (static __device__, no allocs) ----------------
__device__ float g_z[NN * DD];      // h @ W_func^T
__device__ float g_hs[NN * DD];     // h @ W_self^T
__device__ float g_ssrc[NN];
__device__ float g_sdst[NN];
__device__ int   g_deg[NN];
__device__ int   g_incl[NN];
__device__ int   g_bsum[64];
__device__ int   g_bbase[64];
__device__ int   g_cursor[NN];
__device__ int   g_off[NN + 1];
__device__ unsigned long long g_pair[EE];   // (logit<<32 | src) sorted by dst

// ---------------- helpers ----------------
__device__ __forceinline__ unsigned f2tf(float x) {
    unsigned r;
    asm("cvt.rna.tf32.f32 %0, %1;" : "=r"(r) : "f"(x));
    return r;
}

__device__ __forceinline__ void mma_tf32(float* c, unsigned a0, unsigned a1,
                                         unsigned a2, unsigned a3,
                                         unsigned b0, unsigned b1) {
    asm volatile(
        "mma.sync.aligned.m16n8k8.row.col.f32.tf32.tf32.f32 "
        "{%0,%1,%2,%3},{%4,%5,%6,%7},{%8,%9},{%0,%1,%2,%3};\n"
        : "+f"(c[0]), "+f"(c[1]), "+f"(c[2]), "+f"(c[3])
        : "r"(a0), "r"(a1), "r"(a2), "r"(a3), "r"(b0), "r"(b1));
}

__device__ __forceinline__ float warp_sum(float v) {
    #pragma unroll
    for (int o = 16; o; o >>= 1) v += __shfl_xor_sync(0xFFFFFFFFu, v, o);
    return v;
}

// ---------------- K-1: degree histogram (dst only) ----------------
__global__ void k_deg(const int* __restrict__ dst, int E) {
    int e = blockIdx.x * blockDim.x + threadIdx.x;
    if (e < E) atomicAdd(&g_deg[dst[e]], 1);
}

// ---------------- K1: dual tf32 GEMM (h_s and z) + fused rowdots ----------------
__global__ __launch_bounds__(256, 1) void k_gemm_dual(
    const float* __restrict__ h, const float* __restrict__ Ws,
    const float* __restrict__ Wf, const float* __restrict__ Watt, int N) {
    extern __shared__ float smem[];
    float* sH = smem;                                  // 128*132 f32
    unsigned* sW = (unsigned*)(smem + 128 * 132);      // 128*132 tf32 bits

    int tid = threadIdx.x;
    int lane = tid & 31, w = tid >> 5;
    int tg = lane & 3, gid = lane >> 2;
    int row0 = blockIdx.x * 128;

    for (int i = tid; i < 128 * 32; i += 256) {
        int r = i >> 5, c4 = i & 31;
        float4 v = make_float4(0.f, 0.f, 0.f, 0.f);
        if (row0 + r < N) v = ((const float4*)h)[(size_t)(row0 + r) * 32 + c4];
        *(float4*)&sH[r * 132 + c4 * 4] = v;
    }
    __syncthreads();

    unsigned a[2][32];
    int ar0 = w * 16 + gid;
    #pragma unroll
    for (int j = 0; j < 32; j++) {
        a[0][j] = f2tf(sH[ar0 * 132 + tg + 4 * j]);
        a[1][j] = f2tf(sH[(ar0 + 8) * 132 + tg + 4 * j]);
    }

    const float* Wm[2] = {Ws, Wf};
    float* Om[2] = {g_hs, g_z};

    for (int m = 0; m < 2; m++) {
        __syncthreads();
        const float* W = Wm[m];
        for (int i = tid; i < 128 * 128; i += 256) {
            int r = i >> 7, c = i & 127;
            sW[r * 132 + c] = f2tf(W[i]);
        }
        __syncthreads();

        float acc[16][4];
        #pragma unroll
        for (int nt = 0; nt < 16; nt++)
            #pragma unroll
            for (int q = 0; q < 4; q++) acc[nt][q] = 0.f;

        #pragma unroll
        for (int kt = 0; kt < 16; kt++) {
            unsigned a0 = a[0][2 * kt], a2 = a[0][2 * kt + 1];
            unsigned a1 = a[1][2 * kt], a3 = a[1][2 * kt + 1];
            #pragma unroll
            for (int nt = 0; nt < 16; nt++) {
                unsigned b0 = sW[(nt * 8 + gid) * 132 + kt * 8 + tg];
                unsigned b1 = sW[(nt * 8 + gid) * 132 + kt * 8 + tg + 4];
                mma_tf32(acc[nt], a0, a1, a2, a3, b0, b1);
            }
        }

        float* O = Om[m];
        int r1 = row0 + ar0;
        int r2 = r1 + 8;
        #pragma unroll
        for (int nt = 0; nt < 16; nt++) {
            int col = nt * 8 + tg * 2;
            if (r1 < N) *(float2*)&O[(size_t)r1 * 128 + col] = make_float2(acc[nt][0], acc[nt][1]);
            if (r2 < N) *(float2*)&O[(size_t)r2 * 128 + col] = make_float2(acc[nt][2], acc[nt][3]);
        }

        if (m == 1) {
            // fused rowdots: s_src = z·Wa[0:128], s_dst = z·Wa[128:256]
            float p1a = 0.f, p1b = 0.f, p2a = 0.f, p2b = 0.f;
            #pragma unroll
            for (int nt = 0; nt < 16; nt++) {
                int c0 = nt * 8 + tg * 2;
                float wa0 = Watt[c0],        wa1 = Watt[c0 + 1];
                float wb0 = Watt[128 + c0],  wb1 = Watt[128 + c0 + 1];
                p1a += acc[nt][0] * wa0 + acc[nt][1] * wa1;
                p1b += acc[nt][0] * wb0 + acc[nt][1] * wb1;
                p2a += acc[nt][2] * wa0 + acc[nt][3] * wa1;
                p2b += acc[nt][2] * wb0 + acc[nt][3] * wb1;
            }
            #pragma unroll
            for (int o = 1; o < 4; o <<= 1) {
                p1a += __shfl_xor_sync(0xFFFFFFFFu, p1a, o);
                p1b += __shfl_xor_sync(0xFFFFFFFFu, p1b, o);
                p2a += __shfl_xor_sync(0xFFFFFFFFu, p2a, o);
                p2b += __shfl_xor_sync(0xFFFFFFFFu, p2b, o);
            }
            if (tg == 0) {
                if (r1 < N) { g_ssrc[r1] = p1a; g_sdst[r1] = p1b; }
                if (r2 < N) { g_ssrc[r2] = p2a; g_sdst[r2] = p2b; }
            }
        }
    }
}

// ---------------- K3: edge logits (8 edges/warp) + direct dst-sorted scatter ----------------
__global__ void k_edge_logits(const float* __restrict__ ew,
                              const float* __restrict__ Watt,
                              const int* __restrict__ src,
                              const int* __restrict__ dst, int E) {
    int wid = (blockIdx.x * blockDim.x + threadIdx.x) >> 5;
    int lane = threadIdx.x & 31;
    int base = wid * 8;
    if (base >= E) return;

    float4 w4 = ((const float4*)Watt)[64 + lane];   // wa[256:384]

    float s[8];
    #pragma unroll
    for (int j = 0; j < 8; j++) {
        float4 e4 = make_float4(0.f, 0.f, 0.f, 0.f);
        if (base + j < E) e4 = ((const float4*)ew)[(size_t)(base + j) * 32 + lane];
        s[j] = e4.x * w4.x + e4.y * w4.y + e4.z * w4.z + e4.w * w4.w;
    }

    #pragma unroll
    for (int o = 16; o; o >>= 1) {
        #pragma unroll
        for (int j = 0; j < 8; j++)
            s[j] += __shfl_xor_sync(0xFFFFFFFFu, s[j], o);
    }

    if (lane < 8) {
        int e = base + lane;
        if (e < E) {
            float se = s[0];
            #pragma unroll
            for (int j = 1; j < 8; j++)
                if (lane == j) se = s[j];
            int d = dst[e];
            int sc = src[e];
            float l = g_ssrc[sc] + g_sdst[d] + se;
            l = l > 0.f ? l : 0.01f * l;
            int p = atomicAdd(&g_cursor[d], 1);
            g_pair[p] = ((unsigned long long)__float_as_uint(l) << 32) |
                        (unsigned)sc;
        }
    }
}

// ---------------- K4a/b/c: exclusive scan of degrees ----------------
__global__ void k_scan1(int N) {
    __shared__ int s[1024];
    int i = blockIdx.x * 1024 + threadIdx.x;
    int v = (i < N) ? g_deg[i] : 0;
    s[threadIdx.x] = v;
    #pragma unroll
    for (int off = 1; off < 1024; off <<= 1) {
        __syncthreads();
        int t = (threadIdx.x >= off) ? s[threadIdx.x - off] : 0;
        __syncthreads();
        s[threadIdx.x] += t;
    }
    if (i < N) g_incl[i] = s[threadIdx.x];
    if (threadIdx.x == 1023) g_bsum[blockIdx.x] = s[1023];
}

__global__ void k_scan2(int nb) {
    if (threadIdx.x == 0) {
        int base = 0;
        for (int b = 0; b < nb; b++) { g_bbase[b] = base; base += g_bsum[b]; }
    }
}

__global__ void k_scan3(int N, int E) {
    int i = blockIdx.x * blockDim.x + threadIdx.x;
    if (i >= N) return;
    int start = g_incl[i] - g_deg[i] + g_bbase[i >> 10];
    g_off[i] = start;
    g_cursor[i] = start;
    if (i == N - 1) g_off[N] = start + g_deg[i];
}

// ---------------- K6: per-dst softmax + weighted gather + epilogue ----------------
__global__ void k_aggregate(const float* __restrict__ h,
                            float* __restrict__ out, int N) {
    int wid = (blockIdx.x * blockDim.x + threadIdx.x) >> 5;
    int lane = threadIdx.x & 31;
    if (wid >= N) return;

    int beg = g_off[wid], end = g_off[wid + 1];
    float4 hv = ((const float4*)h)[(size_t)wid * 32 + lane];
    float4 res;
    int deg = end - beg;

    if (deg == 0) {
        res.x = hv.x + fmaxf(hv.x, 0.f);
        res.y = hv.y + fmaxf(hv.y, 0.f);
        res.z = hv.z + fmaxf(hv.z, 0.f);
        res.w = hv.w + fmaxf(hv.w, 0.f);
    } else {
        float4 acc = make_float4(0.f, 0.f, 0.f, 0.f);
        float denom = 0.f;

        if (deg <= 32) {
            // fast path: single read of pairs, max+exp from registers
            unsigned long long u = 0;
            float lg = -INFINITY;
            if (lane < deg) {
                u = g_pair[beg + lane];
                lg = __uint_as_float((unsigned)(u >> 32));
            }
            float m = lg;
            #pragma unroll
            for (int o = 16; o; o >>= 1)
                m = fmaxf(m, __shfl_xor_sync(0xFFFFFFFFu, m, o));
            float wl = (lane < deg) ? __expf(lg - m) : 0.f;
            int sv = (int)(unsigned)u;
            denom = wl;

            int k = 0;
            for (; k + 8 <= deg; k += 8) {
                float wb[8]; int ab[8];
                #pragma unroll
                for (int j = 0; j < 8; j++) {
                    wb[j] = __shfl_sync(0xFFFFFFFFu, wl, k + j);
                    ab[j] = __shfl_sync(0xFFFFFFFFu, sv, k + j);
                }
                float4 zb[8];
                #pragma unroll
                for (int j = 0; j < 8; j++)
                    zb[j] = ((const float4*)g_z)[(size_t)ab[j] * 32 + lane];
                #pragma unroll
                for (int j = 0; j < 8; j++) {
                    acc.x += wb[j] * zb[j].x;
                    acc.y += wb[j] * zb[j].y;
                    acc.z += wb[j] * zb[j].z;
                    acc.w += wb[j] * zb[j].w;
                }
            }
            for (; k < deg; k++) {
                float w0 = __shfl_sync(0xFFFFFFFFu, wl, k);
                int   a0 = __shfl_sync(0xFFFFFFFFu, sv, k);
                float4 z0 = ((const float4*)g_z)[(size_t)a0 * 32 + lane];
                acc.x += w0 * z0.x;
                acc.y += w0 * z0.y;
                acc.z += w0 * z0.z;
                acc.w += w0 * z0.w;
            }
        } else {
            // general path: two passes
            float m = -INFINITY;
            for (int i = beg + lane; i < end; i += 32)
                m = fmaxf(m, __uint_as_float((unsigned)(g_pair[i] >> 32)));
            #pragma unroll
            for (int o = 16; o; o >>= 1)
                m = fmaxf(m, __shfl_xor_sync(0xFFFFFFFFu, m, o));

            for (int i = beg; i < end; i += 32) {
                int cnt = end - i; if (cnt > 32) cnt = 32;
                float wl = 0.f;
                int sv = 0;
                if (lane < cnt) {
                    unsigned long long u = g_pair[i + lane];
                    wl = __expf(__uint_as_float((unsigned)(u >> 32)) - m);
                    sv = (int)(unsigned)u;
                }
                denom += wl;
                int k = 0;
                for (; k + 8 <= cnt; k += 8) {
                    float wb[8]; int ab[8];
                    #pragma unroll
                    for (int j = 0; j < 8; j++) {
                        wb[j] = __shfl_sync(0xFFFFFFFFu, wl, k + j);
                        ab[j] = __shfl_sync(0xFFFFFFFFu, sv, k + j);
                    }
                    float4 zb[8];
                    #pragma unroll
                    for (int j = 0; j < 8; j++)
                        zb[j] = ((const float4*)g_z)[(size_t)ab[j] * 32 + lane];
                    #pragma unroll
                    for (int j = 0; j < 8; j++) {
                        acc.x += wb[j] * zb[j].x;
                        acc.y += wb[j] * zb[j].y;
                        acc.z += wb[j] * zb[j].z;
                        acc.w += wb[j] * zb[j].w;
                    }
                }
                for (; k < cnt; k++) {
                    float w0 = __shfl_sync(0xFFFFFFFFu, wl, k);
                    int   a0 = __shfl_sync(0xFFFFFFFFu, sv, k);
                    float4 z0 = ((const float4*)g_z)[(size_t)a0 * 32 + lane];
                    acc.x += w0 * z0.x;
                    acc.y += w0 * z0.y;
                    acc.z += w0 * z0.z;
                    acc.w += w0 * z0.w;
                }
            }
        }

        denom = warp_sum(denom);
        float inv = 1.f / fmaxf(denom, 1e-9f);
        float4 hs = ((const float4*)g_hs)[(size_t)wid * 32 + lane];
        float tx = hs.x + acc.x * inv;
        float ty = hs.y + acc.y * inv;
        float tz = hs.z + acc.z * inv;
        float tw = hs.w + acc.w * inv;
        res.x = hv.x + fmaxf(tx, 0.f);
        res.y = hv.y + fmaxf(ty, 0.f);
        res.z = hv.z + fmaxf(tz, 0.f);
        res.w = hv.w + fmaxf(tw, 0.f);
    }
    ((float4*)out)[(size_t)wid * 32 + lane] = res;
}

// ---------------- launch ----------------
extern "C" void kernel_launch(void* const* d_in, const int* in_sizes, int n_in,
                              void* d_out, int out_size) {
    const float* h    = (const float*)d_in[0];
    const float* ew   = (const float*)d_in[1];
    const float* Ws   = (const float*)d_in[2];
    const float* Wf   = (const float*)d_in[3];
    const float* Watt = (const float*)d_in[4];
    const int*   src  = (const int*)d_in[5];
    const int*   dst  = (const int*)d_in[6];
    float* out = (float*)d_out;

    int N = in_sizes[0] / DD;
    int E = in_sizes[5];

    size_t gemm_smem = (size_t)(128 * 132) * 4 * 2;
    cudaFuncSetAttribute(k_gemm_dual, cudaFuncAttributeMaxDynamicSharedMemorySize,
                         (int)gemm_smem);

    void* degp = nullptr;
    cudaGetSymbolAddress(&degp, g_deg);
    cudaMemsetAsync(degp, 0, (size_t)N * sizeof(int));

    k_deg<<<(E + 255) / 256, 256>>>(dst, E);

    int nb = (N + 1023) / 1024;
    k_scan1<<<nb, 1024>>>(N);
    k_scan2<<<1, 32>>>(nb);
    k_scan3<<<(N + 255) / 256, 256>>>(N, E);

    k_gemm_dual<<<(N + 127) / 128, 256, gemm_smem>>>(h, Ws, Wf, Watt, N);

    int ewarps = (E + 7) / 8;
    k_edge_logits<<<(ewarps + 7) / 8, 256>>>(ew, Watt, src, dst, E);

    k_aggregate<<<(N + 7) / 8, 256>>>(h, out, N);
}

// round 10
// speedup vs baseline: 1.2859x; 1.0253x over previous
#include <cuda_runtime.h>
#include <math.h>

#define NN 50000
#define EE 800000
#define DD 128

// ---------------- scratch (static __device__, no allocs) ----------------
__device__ float g_z[NN * DD];      // h @ W_func^T
__device__ float g_hs[NN * DD];     // h @ W_self^T
__device__ float g_ssrc[NN];
__device__ float g_sdst[NN];
__device__ float g_se[EE];          // per-edge attention dot (edge_w . wa[256:384])
__device__ int   g_deg[NN];
__device__ int   g_incl[NN];
__device__ int   g_bsum[64];
__device__ int   g_bbase[64];
__device__ int   g_cursor[NN];
__device__ int   g_off[NN + 1];
__device__ unsigned long long g_pair[EE];   // (logit<<32 | src) sorted by dst

// ---------------- helpers ----------------
__device__ __forceinline__ unsigned f2tf(float x) {
    unsigned r;
    asm("cvt.rna.tf32.f32 %0, %1;" : "=r"(r) : "f"(x));
    return r;
}

__device__ __forceinline__ void mma_tf32(float* c, unsigned a0, unsigned a1,
                                         unsigned a2, unsigned a3,
                                         unsigned b0, unsigned b1) {
    asm volatile(
        "mma.sync.aligned.m16n8k8.row.col.f32.tf32.tf32.f32 "
        "{%0,%1,%2,%3},{%4,%5,%6,%7},{%8,%9},{%0,%1,%2,%3};\n"
        : "+f"(c[0]), "+f"(c[1]), "+f"(c[2]), "+f"(c[3])
        : "r"(a0), "r"(a1), "r"(a2), "r"(a3), "r"(b0), "r"(b1));
}

__device__ __forceinline__ float warp_sum(float v) {
    #pragma unroll
    for (int o = 16; o; o >>= 1) v += __shfl_xor_sync(0xFFFFFFFFu, v, o);
    return v;
}

// ---------------- degree histogram (dst only) ----------------
__global__ void k_deg(const int* __restrict__ dst, int E) {
    int e = blockIdx.x * blockDim.x + threadIdx.x;
    if (e < E) atomicAdd(&g_deg[dst[e]], 1);
}

// ---------------- dual tf32 GEMM (h_s and z) + fused rowdots ----------------
__global__ __launch_bounds__(256, 1) void k_gemm_dual(
    const float* __restrict__ h, const float* __restrict__ Ws,
    const float* __restrict__ Wf, const float* __restrict__ Watt, int N) {
    extern __shared__ float smem[];
    float* sH = smem;                                  // 128*132 f32
    unsigned* sW = (unsigned*)(smem + 128 * 132);      // 128*132 tf32 bits

    int tid = threadIdx.x;
    int lane = tid & 31, w = tid >> 5;
    int tg = lane & 3, gid = lane >> 2;
    int row0 = blockIdx.x * 128;

    for (int i = tid; i < 128 * 32; i += 256) {
        int r = i >> 5, c4 = i & 31;
        float4 v = make_float4(0.f, 0.f, 0.f, 0.f);
        if (row0 + r < N) v = ((const float4*)h)[(size_t)(row0 + r) * 32 + c4];
        *(float4*)&sH[r * 132 + c4 * 4] = v;
    }
    __syncthreads();

    unsigned a[2][32];
    int ar0 = w * 16 + gid;
    #pragma unroll
    for (int j = 0; j < 32; j++) {
        a[0][j] = f2tf(sH[ar0 * 132 + tg + 4 * j]);
        a[1][j] = f2tf(sH[(ar0 + 8) * 132 + tg + 4 * j]);
    }

    const float* Wm[2] = {Ws, Wf};
    float* Om[2] = {g_hs, g_z};

    for (int m = 0; m < 2; m++) {
        __syncthreads();
        const float* W = Wm[m];
        for (int i = tid; i < 128 * 128; i += 256) {
            int r = i >> 7, c = i & 127;
            sW[r * 132 + c] = f2tf(W[i]);
        }
        __syncthreads();

        float acc[16][4];
        #pragma unroll
        for (int nt = 0; nt < 16; nt++)
            #pragma unroll
            for (int q = 0; q < 4; q++) acc[nt][q] = 0.f;

        #pragma unroll
        for (int kt = 0; kt < 16; kt++) {
            unsigned a0 = a[0][2 * kt], a2 = a[0][2 * kt + 1];
            unsigned a1 = a[1][2 * kt], a3 = a[1][2 * kt + 1];
            #pragma unroll
            for (int nt = 0; nt < 16; nt++) {
                unsigned b0 = sW[(nt * 8 + gid) * 132 + kt * 8 + tg];
                unsigned b1 = sW[(nt * 8 + gid) * 132 + kt * 8 + tg + 4];
                mma_tf32(acc[nt], a0, a1, a2, a3, b0, b1);
            }
        }

        float* O = Om[m];
        int r1 = row0 + ar0;
        int r2 = r1 + 8;
        #pragma unroll
        for (int nt = 0; nt < 16; nt++) {
            int col = nt * 8 + tg * 2;
            if (r1 < N) *(float2*)&O[(size_t)r1 * 128 + col] = make_float2(acc[nt][0], acc[nt][1]);
            if (r2 < N) *(float2*)&O[(size_t)r2 * 128 + col] = make_float2(acc[nt][2], acc[nt][3]);
        }

        if (m == 1) {
            // fused rowdots: s_src = z·Wa[0:128], s_dst = z·Wa[128:256]
            float p1a = 0.f, p1b = 0.f, p2a = 0.f, p2b = 0.f;
            #pragma unroll
            for (int nt = 0; nt < 16; nt++) {
                int c0 = nt * 8 + tg * 2;
                float wa0 = Watt[c0],        wa1 = Watt[c0 + 1];
                float wb0 = Watt[128 + c0],  wb1 = Watt[128 + c0 + 1];
                p1a += acc[nt][0] * wa0 + acc[nt][1] * wa1;
                p1b += acc[nt][0] * wb0 + acc[nt][1] * wb1;
                p2a += acc[nt][2] * wa0 + acc[nt][3] * wa1;
                p2b += acc[nt][2] * wb0 + acc[nt][3] * wb1;
            }
            #pragma unroll
            for (int o = 1; o < 4; o <<= 1) {
                p1a += __shfl_xor_sync(0xFFFFFFFFu, p1a, o);
                p1b += __shfl_xor_sync(0xFFFFFFFFu, p1b, o);
                p2a += __shfl_xor_sync(0xFFFFFFFFu, p2a, o);
                p2b += __shfl_xor_sync(0xFFFFFFFFu, p2b, o);
            }
            if (tg == 0) {
                if (r1 < N) { g_ssrc[r1] = p1a; g_sdst[r1] = p1b; }
                if (r2 < N) { g_ssrc[r2] = p2a; g_sdst[r2] = p2b; }
            }
        }
    }
}

// ---------------- edge pre-dot: s_e = edge_w . wa[256:384]  (8 edges/warp) ----------------
__global__ void k_edge_se(const float* __restrict__ ew,
                          const float* __restrict__ Watt, int E) {
    int wid = (blockIdx.x * blockDim.x + threadIdx.x) >> 5;
    int lane = threadIdx.x & 31;
    int base = wid * 8;
    if (base >= E) return;

    float4 w4 = ((const float4*)Watt)[64 + lane];   // wa[256:384]

    float s[8];
    #pragma unroll
    for (int j = 0; j < 8; j++) {
        float4 e4 = make_float4(0.f, 0.f, 0.f, 0.f);
        if (base + j < E) e4 = ((const float4*)ew)[(size_t)(base + j) * 32 + lane];
        s[j] = e4.x * w4.x + e4.y * w4.y + e4.z * w4.z + e4.w * w4.w;
    }

    #pragma unroll
    for (int o = 16; o; o >>= 1) {
        #pragma unroll
        for (int j = 0; j < 8; j++)
            s[j] += __shfl_xor_sync(0xFFFFFFFFu, s[j], o);
    }

    if (lane < 8) {
        int e = base + lane;
        if (e < E) {
            float se = s[0];
            #pragma unroll
            for (int j = 1; j < 8; j++)
                if (lane == j) se = s[j];
            g_se[e] = se;
        }
    }
}

// ---------------- edge final: logit + dst-sorted scatter ----------------
__global__ void k_edge_final(const int* __restrict__ src,
                             const int* __restrict__ dst, int E) {
    int e = blockIdx.x * blockDim.x + threadIdx.x;
    if (e >= E) return;
    int d = dst[e];
    int sc = src[e];
    float l = g_ssrc[sc] + g_sdst[d] + g_se[e];
    l = l > 0.f ? l : 0.01f * l;
    int p = atomicAdd(&g_cursor[d], 1);
    g_pair[p] = ((unsigned long long)__float_as_uint(l) << 32) | (unsigned)sc;
}

// ---------------- exclusive scan of degrees ----------------
__global__ void k_scan1(int N) {
    __shared__ int s[1024];
    int i = blockIdx.x * 1024 + threadIdx.x;
    int v = (i < N) ? g_deg[i] : 0;
    s[threadIdx.x] = v;
    #pragma unroll
    for (int off = 1; off < 1024; off <<= 1) {
        __syncthreads();
        int t = (threadIdx.x >= off) ? s[threadIdx.x - off] : 0;
        __syncthreads();
        s[threadIdx.x] += t;
    }
    if (i < N) g_incl[i] = s[threadIdx.x];
    if (threadIdx.x == 1023) g_bsum[blockIdx.x] = s[1023];
}

__global__ void k_scan2(int nb) {
    if (threadIdx.x == 0) {
        int base = 0;
        for (int b = 0; b < nb; b++) { g_bbase[b] = base; base += g_bsum[b]; }
    }
}

__global__ void k_scan3(int N, int E) {
    int i = blockIdx.x * blockDim.x + threadIdx.x;
    if (i >= N) return;
    int start = g_incl[i] - g_deg[i] + g_bbase[i >> 10];
    g_off[i] = start;
    g_cursor[i] = start;
    if (i == N - 1) g_off[N] = start + g_deg[i];
}

// ---------------- per-dst softmax + weighted gather + epilogue ----------------
__global__ void k_aggregate(const float* __restrict__ h,
                            float* __restrict__ out, int N) {
    int wid = (blockIdx.x * blockDim.x + threadIdx.x) >> 5;
    int lane = threadIdx.x & 31;
    if (wid >= N) return;

    int beg = g_off[wid], end = g_off[wid + 1];
    float4 hv = ((const float4*)h)[(size_t)wid * 32 + lane];
    float4 res;
    int deg = end - beg;

    if (deg == 0) {
        res.x = hv.x + fmaxf(hv.x, 0.f);
        res.y = hv.y + fmaxf(hv.y, 0.f);
        res.z = hv.z + fmaxf(hv.z, 0.f);
        res.w = hv.w + fmaxf(hv.w, 0.f);
    } else {
        float4 acc = make_float4(0.f, 0.f, 0.f, 0.f);
        float denom = 0.f;

        if (deg <= 32) {
            unsigned long long u = 0;
            float lg = -INFINITY;
            if (lane < deg) {
                u = g_pair[beg + lane];
                lg = __uint_as_float((unsigned)(u >> 32));
            }
            float m = lg;
            #pragma unroll
            for (int o = 16; o; o >>= 1)
                m = fmaxf(m, __shfl_xor_sync(0xFFFFFFFFu, m, o));
            float wl = (lane < deg) ? __expf(lg - m) : 0.f;
            int sv = (int)(unsigned)u;
            denom = wl;

            int k = 0;
            for (; k + 8 <= deg; k += 8) {
                float wb[8]; int ab[8];
                #pragma unroll
                for (int j = 0; j < 8; j++) {
                    wb[j] = __shfl_sync(0xFFFFFFFFu, wl, k + j);
                    ab[j] = __shfl_sync(0xFFFFFFFFu, sv, k + j);
                }
                float4 zb[8];
                #pragma unroll
                for (int j = 0; j < 8; j++)
                    zb[j] = ((const float4*)g_z)[(size_t)ab[j] * 32 + lane];
                #pragma unroll
                for (int j = 0; j < 8; j++) {
                    acc.x += wb[j] * zb[j].x;
                    acc.y += wb[j] * zb[j].y;
                    acc.z += wb[j] * zb[j].z;
                    acc.w += wb[j] * zb[j].w;
                }
            }
            for (; k < deg; k++) {
                float w0 = __shfl_sync(0xFFFFFFFFu, wl, k);
                int   a0 = __shfl_sync(0xFFFFFFFFu, sv, k);
                float4 z0 = ((const float4*)g_z)[(size_t)a0 * 32 + lane];
                acc.x += w0 * z0.x;
                acc.y += w0 * z0.y;
                acc.z += w0 * z0.z;
                acc.w += w0 * z0.w;
            }
        } else {
            float m = -INFINITY;
            for (int i = beg + lane; i < end; i += 32)
                m = fmaxf(m, __uint_as_float((unsigned)(g_pair[i] >> 32)));
            #pragma unroll
            for (int o = 16; o; o >>= 1)
                m = fmaxf(m, __shfl_xor_sync(0xFFFFFFFFu, m, o));

            for (int i = beg; i < end; i += 32) {
                int cnt = end - i; if (cnt > 32) cnt = 32;
                float wl = 0.f;
                int sv = 0;
                if (lane < cnt) {
                    unsigned long long u = g_pair[i + lane];
                    wl = __expf(__uint_as_float((unsigned)(u >> 32)) - m);
                    sv = (int)(unsigned)u;
                }
                denom += wl;
                int k = 0;
                for (; k + 8 <= cnt; k += 8) {
                    float wb[8]; int ab[8];
                    #pragma unroll
                    for (int j = 0; j < 8; j++) {
                        wb[j] = __shfl_sync(0xFFFFFFFFu, wl, k + j);
                        ab[j] = __shfl_sync(0xFFFFFFFFu, sv, k + j);
                    }
                    float4 zb[8];
                    #pragma unroll
                    for (int j = 0; j < 8; j++)
                        zb[j] = ((const float4*)g_z)[(size_t)ab[j] * 32 + lane];
                    #pragma unroll
                    for (int j = 0; j < 8; j++) {
                        acc.x += wb[j] * zb[j].x;
                        acc.y += wb[j] * zb[j].y;
                        acc.z += wb[j] * zb[j].z;
                        acc.w += wb[j] * zb[j].w;
                    }
                }
                for (; k < cnt; k++) {
                    float w0 = __shfl_sync(0xFFFFFFFFu, wl, k);
                    int   a0 = __shfl_sync(0xFFFFFFFFu, sv, k);
                    float4 z0 = ((const float4*)g_z)[(size_t)a0 * 32 + lane];
                    acc.x += w0 * z0.x;
                    acc.y += w0 * z0.y;
                    acc.z += w0 * z0.z;
                    acc.w += w0 * z0.w;
                }
            }
        }

        denom = warp_sum(denom);
        float inv = 1.f / fmaxf(denom, 1e-9f);
        float4 hs = ((const float4*)g_hs)[(size_t)wid * 32 + lane];
        float tx = hs.x + acc.x * inv;
        float ty = hs.y + acc.y * inv;
        float tz = hs.z + acc.z * inv;
        float tw = hs.w + acc.w * inv;
        res.x = hv.x + fmaxf(tx, 0.f);
        res.y = hv.y + fmaxf(ty, 0.f);
        res.z = hv.z + fmaxf(tz, 0.f);
        res.w = hv.w + fmaxf(tw, 0.f);
    }
    ((float4*)out)[(size_t)wid * 32 + lane] = res;
}

// ---------------- launch (fork/join across 3 streams) ----------------
extern "C" void kernel_launch(void* const* d_in, const int* in_sizes, int n_in,
                              void* d_out, int out_size) {
    const float* h    = (const float*)d_in[0];
    const float* ew   = (const float*)d_in[1];
    const float* Ws   = (const float*)d_in[2];
    const float* Wf   = (const float*)d_in[3];
    const float* Watt = (const float*)d_in[4];
    const int*   src  = (const int*)d_in[5];
    const int*   dst  = (const int*)d_in[6];
    float* out = (float*)d_out;

    int N = in_sizes[0] / DD;
    int E = in_sizes[5];

    static cudaStream_t sA = nullptr, sB = nullptr;
    static cudaEvent_t evFork = nullptr, evA = nullptr, evB = nullptr;
    if (sA == nullptr) {
        cudaStreamCreateWithFlags(&sA, cudaStreamNonBlocking);
        cudaStreamCreateWithFlags(&sB, cudaStreamNonBlocking);
        cudaEventCreateWithFlags(&evFork, cudaEventDisableTiming);
        cudaEventCreateWithFlags(&evA, cudaEventDisableTiming);
        cudaEventCreateWithFlags(&evB, cudaEventDisableTiming);
        size_t gemm_smem = (size_t)(128 * 132) * 4 * 2;
        cudaFuncSetAttribute(k_gemm_dual,
                             cudaFuncAttributeMaxDynamicSharedMemorySize,
                             (int)gemm_smem);
    }
    size_t gemm_smem = (size_t)(128 * 132) * 4 * 2;

    // fork
    cudaEventRecord(evFork, 0);
    cudaStreamWaitEvent(sA, evFork, 0);
    cudaStreamWaitEvent(sB, evFork, 0);

    // stream A: the 410MB edge_w stream (DRAM-bound, no deps)
    int ewarps = (E + 7) / 8;
    k_edge_se<<<(ewarps + 7) / 8, 256, 0, sA>>>(ew, Watt, E);
    cudaEventRecord(evA, sA);

    // stream B: the GEMM (tensor/issue-bound, no smem conflict with A)
    k_gemm_dual<<<(N + 127) / 128, 256, gemm_smem, sB>>>(h, Ws, Wf, Watt, N);
    cudaEventRecord(evB, sB);

    // main stream: deg histogram + scan chain (tiny, hides under A/B)
    void* degp = nullptr;
    cudaGetSymbolAddress(&degp, g_deg);
    cudaMemsetAsync(degp, 0, (size_t)N * sizeof(int), 0);
    k_deg<<<(E + 255) / 256, 256>>>(dst, E);
    int nb = (N + 1023) / 1024;
    k_scan1<<<nb, 1024>>>(N);
    k_scan2<<<1, 32>>>(nb);
    k_scan3<<<(N + 255) / 256, 256>>>(N, E);

    // join
    cudaStreamWaitEvent(0, evA, 0);
    cudaStreamWaitEvent(0, evB, 0);

    // final logit + dst-sorted scatter, then aggregation
    k_edge_final<<<(E + 255) / 256, 256>>>(src, dst, E);
    k_aggregate<<<(N + 7) / 8, 256>>>(h, out, N);
}